// round 10
// baseline (speedup 1.0000x reference)
#include <cuda_runtime.h>
#include <math_constants.h>

#define NBINS 512
#define KNN   16
#define BATCH 8192
#define NROWS 100000
#define CSB   256               // colsum blocks (32 rows each)
#define GRID  (CSB + BATCH)

// Scratch (__device__ globals: allocation-free rule). Zero-initialized at
// module load; the epilogue re-zeros everything after use, so the "== 0 on
// entry" invariant holds for every call (graph replays included).
__device__ float        g_bcol[NBINS];   // atomic column sums
__device__ double       g_sum;           // atomic sum of add*weight
__device__ unsigned int g_count;         // finished-block counter

// Single launch. Blocks [0, CSB): column sums of outputs[0:BATCH, :] into
// g_bcol via atomics (issued first -> pre-warms L2 with the base-row region).
// Blocks [CSB, GRID): gather+max for one batch row each, weighted sum folded
// into g_sum. The LAST block to finish runs the scalar epilogue inline — no
// second kernel launch.
__global__ __launch_bounds__(512, 4)
void fused_kernel(const float* __restrict__ outputs,
                  const float* __restrict__ y,
                  const float* __restrict__ weights,
                  float* __restrict__ out) {
    int tid  = threadIdx.x;
    int warp = tid >> 5;
    int lane = tid & 31;

    if (blockIdx.x < CSB) {
        int r0 = blockIdx.x * (BATCH / CSB);
        float a0 = 0.0f, a1 = 0.0f, a2 = 0.0f, a3 = 0.0f;
#pragma unroll
        for (int r = 0; r < BATCH / CSB; r += 4) {
            a0 += outputs[(size_t)(r0 + r + 0) * NBINS + tid];
            a1 += outputs[(size_t)(r0 + r + 1) * NBINS + tid];
            a2 += outputs[(size_t)(r0 + r + 2) * NBINS + tid];
            a3 += outputs[(size_t)(r0 + r + 3) * NBINS + tid];
        }
        atomicAdd(&g_bcol[tid], (a0 + a1) + (a2 + a3));
    } else {
        // ---- gather + max for batch row b ----
        __shared__ __align__(16) float base[NBINS];
        __shared__ float s_add[KNN];

        int b = blockIdx.x - CSB;
        base[tid] = outputs[(size_t)b * NBINS + tid];
        __syncthreads();

        int idx = (int)y[b * KNN + warp];   // trunc; y >= 0
        const float4* g4 = (const float4*)(outputs + (size_t)idx * NBINS);
        const float4* b4 = (const float4*)base;

        float m = -CUDART_INF_F;
#pragma unroll
        for (int t = 0; t < 4; t++) {
            float4 a = g4[t * 32 + lane];
            float4 c = b4[t * 32 + lane];
            m = fmaxf(m, fmaxf(fmaxf(a.x + c.x, a.y + c.y),
                               fmaxf(a.z + c.z, a.w + c.w)));
        }
#pragma unroll
        for (int o = 16; o; o >>= 1)
            m = fmaxf(m, __shfl_xor_sync(0xFFFFFFFFu, m, o));
        if (lane == 0) s_add[warp] = m;
        __syncthreads();

        if (tid == 0) {
            float s = 0.0f;
#pragma unroll
            for (int k = 0; k < KNN; k++) s += s_add[k];
            out[3 + b] = fmaxf(0.5f, (2.0f - s * (1.0f / KNN)) * 0.5f);
            atomicAdd(&g_sum, (double)(s * weights[b]));
        }
    }

    // ---- last-block epilogue ----
    __shared__ bool is_last;
    __shared__ float smx[16], smn[16];
    if (tid == 0) {
        __threadfence();                       // publish our writes
        unsigned c = atomicAdd(&g_count, 1u);
        is_last = (c == GRID - 1u);
    }
    __syncthreads();
    if (!is_last) return;
    __threadfence();                           // see everyone's writes

    float v   = g_bcol[tid];
    g_bcol[tid] = 0.0f;                        // restore invariant
    float mx = v, mn = v;
#pragma unroll
    for (int o = 16; o; o >>= 1) {
        mx = fmaxf(mx, __shfl_xor_sync(0xFFFFFFFFu, mx, o));
        mn = fminf(mn, __shfl_xor_sync(0xFFFFFFFFu, mn, o));
    }
    if (lane == 0) { smx[warp] = mx; smn[warp] = mn; }
    __syncthreads();

    if (tid == 0) {
        mx = smx[0]; mn = smn[0];
#pragma unroll
        for (int w = 1; w < 16; w++) {
            mx = fmaxf(mx, smx[w]);
            mn = fminf(mn, smn[w]);
        }
        double ds = g_sum;
        g_sum   = 0.0;                         // restore invariants
        g_count = 0u;

        float bb       = mx - mn;
        float target_b = (float)NROWS / (float)NBINS;
        float ratio    = bb / target_b;
        float add_mean = (float)(ds / (double)(BATCH * KNN));
        float d        = 2.0f - add_mean;
        d = d * d;
        out[0] = ratio + d;  // cost
        out[1] = d;          // diff
        out[2] = ratio;      // b / target_b
    }
}

extern "C" void kernel_launch(void* const* d_in, const int* in_sizes, int n_in,
                              void* d_out, int out_size) {
    const float* outputs = (const float*)d_in[0];
    const float* y       = (const float*)d_in[1];
    const float* weights = (const float*)d_in[2];

    fused_kernel<<<GRID, NBINS>>>(outputs, y, weights, (float*)d_out);
}

// round 11
// speedup vs baseline: 1.3634x; 1.3634x over previous
#include <cuda_runtime.h>
#include <math_constants.h>

#define NBINS 512
#define KNN   16
#define BATCH 8192
#define NROWS 100000
#define SLOTS 32          // column-sum accumulator slots (b & 31)

// Scratch (__device__ globals: allocation-free rule). Zero-initialized at
// module load; final_kernel re-zeros everything after use, so the "== 0 on
// entry" invariant holds for every call (graph replays included).
__device__ float  g_part[SLOTS][NBINS];  // sliced atomic column sums
__device__ double g_sum;                 // atomic sum of add*weight

// One uniform launch: block b loads base row b (needed for the gather anyway)
// and folds it into the column sums via sliced atomics — the separate colsum
// pass and its 16 MB of duplicate DRAM reads are gone. Then warp w computes
// add[b,w] = max_j (outputs[nns[b,w], j] + base[j]).
__global__ __launch_bounds__(512, 4)
void fused_kernel(const float* __restrict__ outputs,
                  const float* __restrict__ y,
                  const float* __restrict__ weights,
                  float* __restrict__ booster) {
    __shared__ __align__(16) float base[NBINS];
    __shared__ float s_add[KNN];

    int b    = blockIdx.x;
    int tid  = threadIdx.x;
    int warp = tid >> 5;
    int lane = tid & 31;

    float v = outputs[(size_t)b * NBINS + tid];
    base[tid] = v;
    atomicAdd(&g_part[b & (SLOTS - 1)][tid], v);   // colsum contribution (RED)
    __syncthreads();

    int idx = (int)y[b * KNN + warp];   // trunc; y >= 0
    const float4* g4 = (const float4*)(outputs + (size_t)idx * NBINS);
    const float4* b4 = (const float4*)base;

    float m = -CUDART_INF_F;
#pragma unroll
    for (int t = 0; t < 4; t++) {
        float4 a = g4[t * 32 + lane];
        float4 c = b4[t * 32 + lane];
        m = fmaxf(m, fmaxf(fmaxf(a.x + c.x, a.y + c.y),
                           fmaxf(a.z + c.z, a.w + c.w)));
    }
#pragma unroll
    for (int o = 16; o; o >>= 1)
        m = fmaxf(m, __shfl_xor_sync(0xFFFFFFFFu, m, o));
    if (lane == 0) s_add[warp] = m;
    __syncthreads();

    if (tid == 0) {
        float s = 0.0f;
#pragma unroll
        for (int k = 0; k < KNN; k++) s += s_add[k];
        booster[b] = fmaxf(0.5f, (2.0f - s * (1.0f / KNN)) * 0.5f);
        atomicAdd(&g_sum, (double)(s * weights[b]));
    }
}

// Tiny final: reduce 32 slots -> column sums (coalesced 64KB), min/max, plus
// one scalar read. Restores all zero-invariants for the next call.
__global__ void final_kernel(float* __restrict__ out) {
    __shared__ float smx[16], smn[16];
    int t    = threadIdx.x;
    int warp = t >> 5;
    int lane = t & 31;

    float v = 0.0f;
#pragma unroll
    for (int s = 0; s < SLOTS; s++) {
        v += g_part[s][t];
        g_part[s][t] = 0.0f;           // restore invariant
    }
    float mx = v, mn = v;
#pragma unroll
    for (int o = 16; o; o >>= 1) {
        mx = fmaxf(mx, __shfl_xor_sync(0xFFFFFFFFu, mx, o));
        mn = fminf(mn, __shfl_xor_sync(0xFFFFFFFFu, mn, o));
    }
    if (lane == 0) { smx[warp] = mx; smn[warp] = mn; }
    __syncthreads();

    if (t == 0) {
        mx = smx[0]; mn = smn[0];
#pragma unroll
        for (int w = 1; w < 16; w++) {
            mx = fmaxf(mx, smx[w]);
            mn = fminf(mn, smn[w]);
        }
        double ds = g_sum;
        g_sum = 0.0;                   // restore invariant

        float bb       = mx - mn;
        float target_b = (float)NROWS / (float)NBINS;
        float ratio    = bb / target_b;
        float add_mean = (float)(ds / (double)(BATCH * KNN));
        float d        = 2.0f - add_mean;
        d = d * d;
        out[0] = ratio + d;  // cost
        out[1] = d;          // diff
        out[2] = ratio;      // b / target_b
    }
}

extern "C" void kernel_launch(void* const* d_in, const int* in_sizes, int n_in,
                              void* d_out, int out_size) {
    const float* outputs = (const float*)d_in[0];
    const float* y       = (const float*)d_in[1];
    const float* weights = (const float*)d_in[2];
    float* out = (float*)d_out;

    fused_kernel<<<BATCH, NBINS>>>(outputs, y, weights, out + 3);
    final_kernel<<<1, NBINS>>>(out);
}